// round 15
// baseline (speedup 1.0000x reference)
#include <cuda_runtime.h>
#include <cuda_fp16.h>
#include <cstdint>

#define GS     256
#define NCLS   10
#define NPTS   262144            // 2^18
#define BATCH  16
#define CELLS  (GS * GS)         // 65536
#define TCELLS (BATCH * CELLS)   // 1,048,576
#define PTOT   (BATCH * NPTS)    // 4,194,304
#define CAP    16                // Poisson(4): P(>16) ~ 1e-6
#define IMGS   (BATCH * NCLS)    // 160
#define OUTN   (IMGS * CELLS)    // 10,485,760 floats
#define OVFMAX 8192

// ---------------------------------------------------------------------------
// Scratch — SLOT-MAJOR 32B records (one sector each):
//   uint4 #0 : v0v1, v2v3, v4v5, v6v7   (half2 bit patterns)
//   uint4 #1 : v8v9 (half2), rx (f32 bits), ry (f32 bits), pad
// ---------------------------------------------------------------------------
__device__ uint32_t g_cursor[TCELLS];
__device__ __align__(128) uint4 g_pay[(size_t)CAP * TCELLS * 2];   // 512 MB
__device__ uint32_t g_ovf_cnt;
__device__ float g_ovf[OVFMAX][16];   // cellg(bits), rx, ry, v0..v9

#define CUR4  (TCELLS / 4)
#define CURH  (CUR4 / 2)
__global__ __launch_bounds__(256)
void zero_cursor_a() {
    const int i = blockIdx.x * blockDim.x + threadIdx.x;
    if (i < CURH) ((uint4*)g_cursor)[i] = make_uint4(0u, 0u, 0u, 0u);
}
__global__ __launch_bounds__(256)
void zero_cursor_b() {
    const int i = blockIdx.x * blockDim.x + threadIdx.x;
    if (i < CURH) ((uint4*)g_cursor)[CURH + i] = make_uint4(0u, 0u, 0u, 0u);
    if (i == 0) g_ovf_cnt = 0u;
}

__device__ __forceinline__ uint32_t h2bits(float a, float b) {
    __half2 h = __floats2half2_rn(a, b);
    return *reinterpret_cast<uint32_t*>(&h);
}
__device__ __forceinline__ float2 bits2f2(uint32_t u) {
    __half2 h = *reinterpret_cast<__half2*>(&u);
    return __half22float2(h);
}

// ---------------------------------------------------------------------------
// Pass A: scatter into fixed-capacity slot-major buckets; overflow -> list
// ---------------------------------------------------------------------------
__global__ __launch_bounds__(256)
void scatter_kernel(const float* __restrict__ points,
                    const float* __restrict__ values) {
    const int gid = blockIdx.x * blockDim.x + threadIdx.x;
    const int b = gid >> 18;
    const int n = gid & (NPTS - 1);

    const float* pb = points + (size_t)b * 2 * NPTS;
    const float fx = (pb[n] + 0.5f) * (float)GS;
    const float fy = (pb[NPTS + n] + 0.5f) * (float)GS;
    const float xf = floorf(fx);
    const float yf = floorf(fy);
    const int x = (int)xf;
    const int y = (int)yf;
    const float rx = fx - xf;
    const float ry = fy - yf;
    if (((unsigned)x >= GS) || ((unsigned)y >= GS)) return;

    const float* vb = values + (size_t)b * NCLS * NPTS + n;
    float v[10];
#pragma unroll
    for (int c = 0; c < NCLS; c++) v[c] = vb[(size_t)c * NPTS];

    const int cellg = (b << 16) + (y << 8) + x;
    const uint32_t slot = atomicAdd(&g_cursor[cellg], 1u);

    if (slot < CAP) {
        uint4* dst = &g_pay[((size_t)slot * TCELLS + cellg) * 2];
        const uint4 q0 = make_uint4(h2bits(v[0], v[1]), h2bits(v[2], v[3]),
                                    h2bits(v[4], v[5]), h2bits(v[6], v[7]));
        const uint4 q1 = make_uint4(h2bits(v[8], v[9]),
                                    __float_as_uint(rx), __float_as_uint(ry), 0u);
        __stcs(dst + 0, q0);
        __stcs(dst + 1, q1);
    } else {
        const uint32_t oi = atomicAdd(&g_ovf_cnt, 1u);
        if (oi < OVFMAX) {
            float* r = g_ovf[oi];
            r[0] = __uint_as_float((uint32_t)cellg);
            r[1] = rx;  r[2] = ry;
#pragma unroll
            for (int c = 0; c < NCLS; c++) r[3 + c] = v[c];
        }
    }
}

// ---------------------------------------------------------------------------
// Pass B: HALO reduce — block of 320 threads reads a 17x17 cell halo and
// writes its 16x16x10 output patch exclusively: pure stores, NO atomics,
// NO pre-zeroing. Unroll-2 batched loads + pointer-increment addressing.
// ---------------------------------------------------------------------------
__global__ __launch_bounds__(320, 3)
void reduce_kernel(float* __restrict__ out) {
    const int t = threadIdx.x;         // 0..319; 0..288 own halo cells

    const int blk = blockIdx.x;        // 0..4095
    const int b  = blk >> 8;
    const int tt = blk & 255;
    const int ty = tt >> 4;
    const int tx = tt & 15;

    // halo cell for this thread: (cy, cx) = tile origin - 1 + (hy, hx)
    const int hy = t / 17;
    const int hx = t - 17 * hy;
    const int cy = ty * 16 - 1 + hy;
    const int cx = tx * 16 - 1 + hx;
    const bool active = (t < 289) && ((unsigned)cy < GS) && ((unsigned)cx < GS);
    const int cellg = active ? ((b << 16) + (cy << 8) + cx) : 0;

    const uint32_t raw = active ? g_cursor[cellg] : 0u;
    const uint32_t cnt = raw < CAP ? raw : CAP;
    const uint32_t wmax = __reduce_max_sync(0xFFFFFFFFu, cnt);

    float acc[4][NCLS];
#pragma unroll
    for (int k = 0; k < 4; k++)
#pragma unroll
        for (int c = 0; c < NCLS; c++) acc[k][c] = 0.f;

    const size_t SSTR = (size_t)TCELLS * 2;    // slot stride in uint4 units
    const uint4* pa   = &g_pay[(size_t)cellg * 2];   // slot 0
    const uint4* pb2p = pa + SSTR;                   // slot 1

    for (uint32_t i = 0; i < wmax; i += 2) {
        uint4 q0a, q1a, q0b, q1b;
        const bool pa_on = (i < cnt);
        const bool pb_on = (i + 1 < cnt);
        if (pa_on) {                    // batch both records' loads first (MLP)
            q0a = __ldcs(pa + 0);
            q1a = __ldcs(pa + 1);
        }
        if (pb_on) {
            q0b = __ldcs(pb2p + 0);
            q1b = __ldcs(pb2p + 1);
        }
        pa   += 2 * SSTR;
        pb2p += 2 * SSTR;
        if (pa_on) {
            const float2 f01 = bits2f2(q0a.x), f23 = bits2f2(q0a.y);
            const float2 f45 = bits2f2(q0a.z), f67 = bits2f2(q0a.w);
            const float2 f89 = bits2f2(q1a.x);
            const float rx = __uint_as_float(q1a.y);
            const float ry = __uint_as_float(q1a.z);
            const float wx0 = 1.f - rx, wy0 = 1.f - ry;
            const float w00 = wx0 * wy0, w10 = rx * wy0, w01 = wx0 * ry, w11 = rx * ry;
            const float v[10] = {f01.x, f01.y, f23.x, f23.y, f45.x,
                                 f45.y, f67.x, f67.y, f89.x, f89.y};
#pragma unroll
            for (int c = 0; c < NCLS; c++) {
                acc[0][c] += w00 * v[c];
                acc[1][c] += w10 * v[c];
                acc[2][c] += w01 * v[c];
                acc[3][c] += w11 * v[c];
            }
        }
        if (pb_on) {
            const float2 f01 = bits2f2(q0b.x), f23 = bits2f2(q0b.y);
            const float2 f45 = bits2f2(q0b.z), f67 = bits2f2(q0b.w);
            const float2 f89 = bits2f2(q1b.x);
            const float rx = __uint_as_float(q1b.y);
            const float ry = __uint_as_float(q1b.z);
            const float wx0 = 1.f - rx, wy0 = 1.f - ry;
            const float w00 = wx0 * wy0, w10 = rx * wy0, w01 = wx0 * ry, w11 = rx * ry;
            const float v[10] = {f01.x, f01.y, f23.x, f23.y, f45.x,
                                 f45.y, f67.x, f67.y, f89.x, f89.y};
#pragma unroll
            for (int c = 0; c < NCLS; c++) {
                acc[0][c] += w00 * v[c];
                acc[1][c] += w10 * v[c];
                acc[2][c] += w01 * v[c];
                acc[3][c] += w11 * v[c];
            }
        }
    }

    // stage: st[corner][class][halo cell]  (45.2 KB)
    __shared__ float st[4][NCLS][289];
    if (t < 289) {
#pragma unroll
        for (int k = 0; k < 4; k++)
#pragma unroll
            for (int c = 0; c < NCLS; c++) st[k][c][t] = acc[k][c];
    }
    __syncthreads();

    // assemble the exclusive 16x16x10 patch: 2560 pure stores over 320 threads
    const size_t obase = ((size_t)(b * NCLS)) << 16;
    for (int w = t; w < 256 * NCLS; w += 320) {
        const int c   = w >> 8;
        const int pos = w & 255;
        const int oy  = pos >> 4;
        const int ox  = pos & 15;
        // halo indices of the 4 contributing cells for output (Y,X):
        const int i11 = oy * 17 + ox;        // cell (Y-1, X-1)
        const float v = st[0][c][i11 + 18]   // cell (Y,   X)
                      + st[1][c][i11 + 17]   // cell (Y,   X-1)
                      + st[2][c][i11 + 1]    // cell (Y-1, X)
                      + st[3][c][i11];       // cell (Y-1, X-1)
        const int Y = ty * 16 + oy;
        const int X = tx * 16 + ox;
        out[obase + ((size_t)c << 16) + (Y << 8) + X] = v;
    }
}

// ---------------------------------------------------------------------------
// Pass C: apply rare overflow records with direct atomics (after reduce)
// ---------------------------------------------------------------------------
__global__ __launch_bounds__(256)
void ovf_kernel(float* __restrict__ out) {
    const uint32_t cnt = g_ovf_cnt < OVFMAX ? g_ovf_cnt : OVFMAX;
    for (uint32_t i = blockIdx.x * 256 + threadIdx.x; i < cnt; i += gridDim.x * 256) {
        const float* r = g_ovf[i];
        const uint32_t cellg = __float_as_uint(r[0]);
        const int b = cellg >> 16;
        const int y = (cellg >> 8) & 255;
        const int x = cellg & 255;
        const float rx = r[1], ry = r[2];
        const bool vx1 = (x + 1) < GS;
        const bool vy1 = (y + 1) < GS;
        const float wx0 = 1.f - rx, wy0 = 1.f - ry;
        const float w00 = wx0 * wy0, w10 = rx * wy0, w01 = wx0 * ry, w11 = rx * ry;
        const int i00 = (y << 8) + x;
        float* ob = out + (size_t)b * NCLS * CELLS;
#pragma unroll
        for (int c = 0; c < NCLS; c++) {
            const float v = r[3 + c];
            float* o = ob + ((size_t)c << 16);
            atomicAdd(o + i00, w00 * v);
            if (vx1)        atomicAdd(o + i00 + 1,      w10 * v);
            if (vy1)        atomicAdd(o + i00 + GS,     w01 * v);
            if (vx1 && vy1) atomicAdd(o + i00 + GS + 1, w11 * v);
        }
    }
}

// ---------------------------------------------------------------------------
// Harness entry. Launch order puts reduce at idx 3 (ncu capture slot).
// ---------------------------------------------------------------------------
extern "C" void kernel_launch(void* const* d_in, const int* in_sizes, int n_in,
                              void* d_out, int out_size) {
    const float* points = (const float*)d_in[0];
    const float* values = (const float*)d_in[1];
    float* out = (float*)d_out;

    zero_cursor_a<<<(CURH + 255) / 256, 256>>>();                        // idx 0
    zero_cursor_b<<<(CURH + 255) / 256, 256>>>();                        // idx 1
    scatter_kernel<<<PTOT / 256, 256>>>(points, values);                 // idx 2
    reduce_kernel<<<TCELLS / 256, 320>>>(out);                           // idx 3 (profiled)
    ovf_kernel<<<16, 256>>>(out);                                        // idx 4
}